// round 5
// baseline (speedup 1.0000x reference)
#include <cuda_runtime.h>

// ---------------------------------------------------------------------------
// HybridGCNGraphSAGE: N=100000, E=1250000, dims 64.
//  - CSR-by-dst rebuilt per call (deg -> 3-phase scan -> bin fill).
//  - Gather-then-GEMM: pulls aggregate RAW features (x / g1 / s1) with dinv
//    edge weights; all linear maps applied AFTER aggregation. Pull-1 gathers
//    a single table (x).
//  - GEMM phases use packed fma.rn.f32x2 (FFMA2): weights loaded as b64
//    pairs straight from smem, activations duplicated via mov.b64.
// ---------------------------------------------------------------------------

#define NMAX 100000
#define EMAX 1250000
#define SC   512
#define MAXBLK 256

__device__ int   g_is64;
__device__ int   g_deg[NMAX];
__device__ int   g_rowptr[NMAX + 1];
__device__ int   g_cursor[NMAX];
__device__ int   g_csr[EMAX];
__device__ int   g_bsum[MAXBLK];
__device__ int   g_boff[MAXBLK];
__device__ float g_dinv[NMAX];
__device__ alignas(16) float g_bufA[NMAX * 64];  // gcn-weighted aggregate (layer1: of x, layer2: of g1)
__device__ alignas(16) float g_bufB[NMAX * 64];  // g1
__device__ alignas(16) float g_bufC[NMAX * 64];  // sage mean (x, then s1)
__device__ alignas(16) float g_bufD[NMAX * 64];  // s1

// --------------------------- f32x2 helpers ----------------------------------

__device__ __forceinline__ unsigned long long pk2(float lo, float hi) {
    unsigned long long r;
    asm("mov.b64 %0,{%1,%2};" : "=l"(r) : "f"(lo), "f"(hi));
    return r;
}
__device__ __forceinline__ unsigned long long dup2(float v) {
    unsigned long long r;
    asm("mov.b64 %0,{%1,%1};" : "=l"(r) : "f"(v));
    return r;
}
__device__ __forceinline__ float2 upk2(unsigned long long v) {
    float2 r;
    asm("mov.b64 {%0,%1},%2;" : "=f"(r.x), "=f"(r.y) : "l"(v));
    return r;
}
__device__ __forceinline__ void fma2(unsigned long long& d, unsigned long long a,
                                     unsigned long long b) {
    asm("fma.rn.f32x2 %0,%1,%2,%0;" : "+l"(d) : "l"(a), "l"(b));
}

// --------------------------- dtype detection --------------------------------
__global__ void k_detect(const unsigned int* __restrict__ w, int e) {
    __shared__ int any;
    if (threadIdx.x == 0) any = 0;
    __syncthreads();
    int limit = 2 * e; if (limit > 4096) limit = 4096;
    for (int i = 1 + 2 * (int)threadIdx.x; i < limit; i += 2 * blockDim.x)
        if (w[i] != 0u) any = 1;
    __syncthreads();
    if (threadIdx.x == 0) g_is64 = (any == 0) ? 1 : 0;
}

__device__ __forceinline__ int edge_at(const void* ei, int idx) {
    if (g_is64) return (int)((const long long*)ei)[idx];
    return ((const int*)ei)[idx];
}

// ------------------------------- CSR build ---------------------------------

__global__ void k_zero(int n) {
    int i = blockIdx.x * blockDim.x + threadIdx.x;
    if (i < n) g_deg[i] = 0;
}

__global__ void k_deg(const void* __restrict__ ei, int e) {
    int i = blockIdx.x * blockDim.x + threadIdx.x;
    if (i < e) atomicAdd(&g_deg[edge_at(ei, e + i)], 1);
}

__global__ __launch_bounds__(SC) void k_scan1(int n) {
    __shared__ int ws[SC / 32];
    int i = blockIdx.x * SC + threadIdx.x;
    int v = (i < n) ? g_deg[i] : 0;
#pragma unroll
    for (int o = 16; o; o >>= 1) v += __shfl_down_sync(~0u, v, o);
    if ((threadIdx.x & 31) == 0) ws[threadIdx.x >> 5] = v;
    __syncthreads();
    if (threadIdx.x < 32) {
        int s = (threadIdx.x < SC / 32) ? ws[threadIdx.x] : 0;
#pragma unroll
        for (int o = 16; o; o >>= 1) s += __shfl_down_sync(~0u, s, o);
        if (threadIdx.x == 0) g_bsum[blockIdx.x] = s;
    }
}

__global__ __launch_bounds__(MAXBLK) void k_scan2(int nblk, int n) {
    __shared__ int part[MAXBLK];
    int t = threadIdx.x;
    int v = (t < nblk) ? g_bsum[t] : 0;
    part[t] = v;
    __syncthreads();
#pragma unroll
    for (int o = 1; o < MAXBLK; o <<= 1) {
        int u = (t >= o) ? part[t - o] : 0;
        __syncthreads();
        part[t] += u;
        __syncthreads();
    }
    if (t < nblk) g_boff[t] = part[t] - v;
    if (t == 0) g_rowptr[n] = part[MAXBLK - 1];
}

// local scan + rowptr/cursor + dinv
__global__ __launch_bounds__(SC) void k_scan3(int n) {
    __shared__ int part[SC];
    int t = threadIdx.x;
    int i = blockIdx.x * SC + t;
    int v = (i < n) ? g_deg[i] : 0;
    part[t] = v;
    __syncthreads();
#pragma unroll
    for (int o = 1; o < SC; o <<= 1) {
        int u = (t >= o) ? part[t - o] : 0;
        __syncthreads();
        part[t] += u;
        __syncthreads();
    }
    if (i < n) {
        int ex = g_boff[blockIdx.x] + part[t] - v;
        g_rowptr[i] = ex;
        g_cursor[i] = ex;
        g_dinv[i] = rsqrtf((float)v + 1.f);
    }
}

__global__ void k_fill(const void* __restrict__ ei, int e) {
    int i = blockIdx.x * blockDim.x + threadIdx.x;
    if (i < e) {
        int s = edge_at(ei, i);
        int d = edge_at(ei, e + i);
        int pos = atomicAdd(&g_cursor[d], 1);
        g_csr[pos] = s;
    }
}

// ---------------------------- pull kernels ----------------------------------
// Warp per node. ONE gathers x only (layer1): sage sum + dinv-weighted gcn sum.
__global__ __launch_bounds__(256) void k_pull1(const float* __restrict__ x, int n) {
    int lane = threadIdx.x & 31;
    int i = (blockIdx.x * 256 + threadIdx.x) >> 5;
    if (i >= n) return;
    const float2* __restrict__ tx = reinterpret_cast<const float2*>(x);
    int beg = g_rowptr[i], end = g_rowptr[i + 1];
    float sgx = 0.f, sgy = 0.f, ssx = 0.f, ssy = 0.f;
    int e = beg;
    for (; e + 2 <= end; e += 2) {
        int s0 = g_csr[e], s1 = g_csr[e + 1];
        float d0 = g_dinv[s0], d1 = g_dinv[s1];
        float2 v0 = tx[s0 * 32 + lane];
        float2 v1 = tx[s1 * 32 + lane];
        ssx += v0.x + v1.x; ssy += v0.y + v1.y;
        sgx += d0 * v0.x + d1 * v1.x; sgy += d0 * v0.y + d1 * v1.y;
    }
    if (e < end) {
        int s0 = g_csr[e];
        float d0 = g_dinv[s0];
        float2 v0 = tx[s0 * 32 + lane];
        ssx += v0.x; ssy += v0.y;
        sgx += d0 * v0.x; sgy += d0 * v0.y;
    }
    float dvi = g_dinv[i];
    float2 xi = tx[i * 32 + lane];
    sgx += dvi * xi.x; sgy += dvi * xi.y;
    reinterpret_cast<float2*>(g_bufA)[i * 32 + lane] = make_float2(sgx, sgy);
    int cnt = end - beg;
    float ic = (cnt > 0) ? (1.f / (float)cnt) : 0.f;
    reinterpret_cast<float2*>(g_bufC)[i * 32 + lane] = make_float2(ssx * ic, ssy * ic);
}

// Layer2: gather g1 (dinv-weighted, +self) and s1 (mean).
__global__ __launch_bounds__(256) void k_pull2(int n) {
    int lane = threadIdx.x & 31;
    int i = (blockIdx.x * 256 + threadIdx.x) >> 5;
    if (i >= n) return;
    const float2* __restrict__ tg = reinterpret_cast<const float2*>(g_bufB);
    const float2* __restrict__ ts = reinterpret_cast<const float2*>(g_bufD);
    int beg = g_rowptr[i], end = g_rowptr[i + 1];
    float sgx = 0.f, sgy = 0.f, ssx = 0.f, ssy = 0.f;
    int e = beg;
    for (; e + 2 <= end; e += 2) {
        int s0 = g_csr[e], s1 = g_csr[e + 1];
        float d0 = g_dinv[s0], d1 = g_dinv[s1];
        float2 h0 = tg[s0 * 32 + lane];
        float2 h1 = tg[s1 * 32 + lane];
        float2 v0 = ts[s0 * 32 + lane];
        float2 v1 = ts[s1 * 32 + lane];
        sgx += d0 * h0.x + d1 * h1.x; sgy += d0 * h0.y + d1 * h1.y;
        ssx += v0.x + v1.x; ssy += v0.y + v1.y;
    }
    if (e < end) {
        int s0 = g_csr[e];
        float d0 = g_dinv[s0];
        float2 h0 = tg[s0 * 32 + lane];
        float2 v0 = ts[s0 * 32 + lane];
        sgx += d0 * h0.x; sgy += d0 * h0.y;
        ssx += v0.x; ssy += v0.y;
    }
    float dvi = g_dinv[i];
    float2 gi = tg[i * 32 + lane];
    sgx += dvi * gi.x; sgy += dvi * gi.y;
    reinterpret_cast<float2*>(g_bufA)[i * 32 + lane] = make_float2(sgx, sgy);
    int cnt = end - beg;
    float ic = (cnt > 0) ? (1.f / (float)cnt) : 0.f;
    reinterpret_cast<float2*>(g_bufC)[i * 32 + lane] = make_float2(ssx * ic, ssy * ic);
}

// ---------------------------- tile GEMM helpers -----------------------------

__device__ __forceinline__ void load_w(float (*Ws)[64], const float* __restrict__ W) {
    float4* d = reinterpret_cast<float4*>(&Ws[0][0]);
    const float4* s = reinterpret_cast<const float4*>(W);
    for (int i = threadIdx.x; i < 1024; i += 256) d[i] = s[i];
}

__device__ __forceinline__ void load_in(float (*In)[65], const float* __restrict__ src,
                                        int base, int n) {
    for (int i = threadIdx.x; i < 1024; i += 256) {
        int r = i >> 4, c = (i & 15) << 2;
        float4 v = make_float4(0.f, 0.f, 0.f, 0.f);
        int node = base + r;
        if (node < n) v = *reinterpret_cast<const float4*>(src + node * 64 + c);
        In[r][c] = v.x; In[r][c + 1] = v.y; In[r][c + 2] = v.z; In[r][c + 3] = v.w;
    }
}

// Packed f32x2 GEMM micro-kernel: acc[4 rows][2 col-pairs].
__device__ __forceinline__ void mm2(float (*In)[65], float (*Ws)[64],
                                    unsigned long long acc[4][2], int tx, int ty) {
#pragma unroll 8
    for (int k = 0; k < 64; k++) {
        unsigned long long w01 = *reinterpret_cast<unsigned long long*>(&Ws[k][tx * 4]);
        unsigned long long w23 = *reinterpret_cast<unsigned long long*>(&Ws[k][tx * 4 + 2]);
        unsigned long long a0 = dup2(In[ty * 4 + 0][k]);
        unsigned long long a1 = dup2(In[ty * 4 + 1][k]);
        unsigned long long a2 = dup2(In[ty * 4 + 2][k]);
        unsigned long long a3 = dup2(In[ty * 4 + 3][k]);
        fma2(acc[0][0], a0, w01); fma2(acc[0][1], a0, w23);
        fma2(acc[1][0], a1, w01); fma2(acc[1][1], a1, w23);
        fma2(acc[2][0], a2, w01); fma2(acc[2][1], a2, w23);
        fma2(acc[3][0], a3, w01); fma2(acc[3][1], a3, w23);
    }
}

__device__ __forceinline__ void ln_rows(float (*In)[65], const float* __restrict__ gma,
                                        const float* __restrict__ bta) {
    int t = threadIdx.x;
    if (t < 64) {
        float s = 0.f, sq = 0.f;
#pragma unroll 8
        for (int k = 0; k < 64; k++) { float v = In[t][k]; s += v; sq += v * v; }
        float mu = s * 0.015625f;
        float var = sq * 0.015625f - mu * mu;
        float rs = rsqrtf(var + 1e-5f);
#pragma unroll 8
        for (int k = 0; k < 64; k++) In[t][k] = (In[t][k] - mu) * rs * gma[k] + bta[k];
    }
}

// g1 = relu(dinv*(bufA@W1)+b1) -> bufB ; s1 = relu(bufC@Wl1 + x@Wr1 + bl1) -> bufD
__global__ __launch_bounds__(256) void k_mid(const float* __restrict__ x,
                                             const float* __restrict__ gw1,
                                             const float* __restrict__ gb1,
                                             const float* __restrict__ wl1,
                                             const float* __restrict__ bl1,
                                             const float* __restrict__ wr1, int n) {
    __shared__ alignas(16) float Ws[64][64];
    __shared__ alignas(16) float In[64][65];
    int base = blockIdx.x * 64;
    int tx = threadIdx.x & 15, ty = threadIdx.x >> 4;

    // phase 1: GCN layer-1 linear on aggregated x
    load_w(Ws, gw1); load_in(In, g_bufA, base, n); __syncthreads();
    {
        unsigned long long acc[4][2] = {};
        mm2(In, Ws, acc, tx, ty);
        float4 bv = *reinterpret_cast<const float4*>(gb1 + tx * 4);
#pragma unroll
        for (int i = 0; i < 4; i++) {
            int node = base + ty * 4 + i;
            if (node < n) {
                float dv = g_dinv[node];
                float2 p0 = upk2(acc[i][0]), p1 = upk2(acc[i][1]);
                float4 o = make_float4(fmaxf(dv * p0.x + bv.x, 0.f),
                                       fmaxf(dv * p0.y + bv.y, 0.f),
                                       fmaxf(dv * p1.x + bv.z, 0.f),
                                       fmaxf(dv * p1.y + bv.w, 0.f));
                *reinterpret_cast<float4*>(&g_bufB[node * 64 + tx * 4]) = o;
            }
        }
    }
    __syncthreads();

    // phases 2+3: SAGE layer-1
    unsigned long long accS[4][2];
    {
        float4 bv = *reinterpret_cast<const float4*>(bl1 + tx * 4);
#pragma unroll
        for (int i = 0; i < 4; i++) { accS[i][0] = pk2(bv.x, bv.y); accS[i][1] = pk2(bv.z, bv.w); }
    }
    load_w(Ws, wl1); load_in(In, g_bufC, base, n); __syncthreads();
    mm2(In, Ws, accS, tx, ty); __syncthreads();
    load_w(Ws, wr1); load_in(In, x, base, n); __syncthreads();
    mm2(In, Ws, accS, tx, ty);
#pragma unroll
    for (int i = 0; i < 4; i++) {
        int node = base + ty * 4 + i;
        if (node < n) {
            float2 p0 = upk2(accS[i][0]), p1 = upk2(accS[i][1]);
            float4 o = make_float4(fmaxf(p0.x, 0.f), fmaxf(p0.y, 0.f),
                                   fmaxf(p1.x, 0.f), fmaxf(p1.y, 0.f));
            *reinterpret_cast<float4*>(&g_bufD[node * 64 + tx * 4]) = o;
        }
    }
}

// g2 = dinv*(bufA@W2)+b2; s2 = bufC@Wl2 + bufD@Wr2 + bl2; LN both; out = [g2,s2]@pw + pb
__global__ __launch_bounds__(256) void k_fin(
    const float* __restrict__ gw2, const float* __restrict__ gb2,
    const float* __restrict__ wl2, const float* __restrict__ bl2,
    const float* __restrict__ wr2,
    const float* __restrict__ gcn_g, const float* __restrict__ gcn_b,
    const float* __restrict__ sag_g, const float* __restrict__ sag_b,
    const float* __restrict__ pw, const float* __restrict__ pb,
    float* __restrict__ out, int n) {
    __shared__ alignas(16) float Ws[64][64];
    __shared__ alignas(16) float In[64][65];
    int base = blockIdx.x * 64;
    int tx = threadIdx.x & 15, ty = threadIdx.x >> 4;

    unsigned long long accO[4][2];
    {
        float4 bv = *reinterpret_cast<const float4*>(pb + tx * 4);
#pragma unroll
        for (int i = 0; i < 4; i++) { accO[i][0] = pk2(bv.x, bv.y); accO[i][1] = pk2(bv.z, bv.w); }
    }

    // phase 1: g2 = dinv*(bufA@gw2)+gb2 -> In, LN, then @ pw[0:64]
    load_w(Ws, gw2); load_in(In, g_bufA, base, n); __syncthreads();
    {
        unsigned long long accG[4][2] = {};
        mm2(In, Ws, accG, tx, ty);
        __syncthreads();  // all reads of In/Ws done
        float4 bv = *reinterpret_cast<const float4*>(gb2 + tx * 4);
#pragma unroll
        for (int i = 0; i < 4; i++) {
            int node = base + ty * 4 + i;
            float dv = (node < n) ? g_dinv[node] : 1.f;
            float2 p0 = upk2(accG[i][0]), p1 = upk2(accG[i][1]);
            In[ty * 4 + i][tx * 4 + 0] = dv * p0.x + bv.x;
            In[ty * 4 + i][tx * 4 + 1] = dv * p0.y + bv.y;
            In[ty * 4 + i][tx * 4 + 2] = dv * p1.x + bv.z;
            In[ty * 4 + i][tx * 4 + 3] = dv * p1.y + bv.w;
        }
        load_w(Ws, pw);
        __syncthreads();
        ln_rows(In, gcn_g, gcn_b);
        __syncthreads();
        mm2(In, Ws, accO, tx, ty);
    }
    __syncthreads();

    // phases 2+3: s2 = bufC@wl2 + bufD@wr2 + bl2
    unsigned long long accS[4][2];
    {
        float4 bv = *reinterpret_cast<const float4*>(bl2 + tx * 4);
#pragma unroll
        for (int i = 0; i < 4; i++) { accS[i][0] = pk2(bv.x, bv.y); accS[i][1] = pk2(bv.z, bv.w); }
    }
    load_w(Ws, wl2); load_in(In, g_bufC, base, n); __syncthreads();
    mm2(In, Ws, accS, tx, ty); __syncthreads();
    load_w(Ws, wr2); load_in(In, g_bufD, base, n); __syncthreads();
    mm2(In, Ws, accS, tx, ty);
    __syncthreads();  // reads done before In overwrite
#pragma unroll
    for (int i = 0; i < 4; i++) {
        float2 p0 = upk2(accS[i][0]), p1 = upk2(accS[i][1]);
        In[ty * 4 + i][tx * 4 + 0] = p0.x;
        In[ty * 4 + i][tx * 4 + 1] = p0.y;
        In[ty * 4 + i][tx * 4 + 2] = p1.x;
        In[ty * 4 + i][tx * 4 + 3] = p1.y;
    }
    load_w(Ws, pw + 64 * 64);
    __syncthreads();
    ln_rows(In, sag_g, sag_b);
    __syncthreads();
    mm2(In, Ws, accO, tx, ty);

#pragma unroll
    for (int i = 0; i < 4; i++) {
        int node = base + ty * 4 + i;
        if (node < n) {
            float2 p0 = upk2(accO[i][0]), p1 = upk2(accO[i][1]);
            *reinterpret_cast<float4*>(&out[node * 64 + tx * 4]) =
                make_float4(p0.x, p0.y, p1.x, p1.y);
        }
    }
}

// --------------------------------- launch -----------------------------------

extern "C" void kernel_launch(void* const* d_in, const int* in_sizes, int n_in,
                              void* d_out, int out_size) {
    const float* x      = (const float*)d_in[0];
    const void*  ei     = d_in[1];
    const float* gcn_w1 = (const float*)d_in[2];
    const float* gcn_b1 = (const float*)d_in[3];
    const float* gcn_w2 = (const float*)d_in[4];
    const float* gcn_b2 = (const float*)d_in[5];
    const float* wl1    = (const float*)d_in[6];
    const float* bl1    = (const float*)d_in[7];
    const float* wr1    = (const float*)d_in[8];
    const float* wl2    = (const float*)d_in[9];
    const float* bl2    = (const float*)d_in[10];
    const float* wr2    = (const float*)d_in[11];
    const float* lg     = (const float*)d_in[12];
    const float* lb     = (const float*)d_in[13];
    const float* sg     = (const float*)d_in[14];
    const float* sb     = (const float*)d_in[15];
    const float* pw     = (const float*)d_in[16];
    const float* pb     = (const float*)d_in[17];
    float* out = (float*)d_out;

    int n = in_sizes[0] / 64;
    int e = in_sizes[1] / 2;

    int grid64 = (n + 63) / 64;
    int gridE  = (e + 255) / 256;
    int gridP  = (n + 7) / 8;
    int nblk   = (n + SC - 1) / SC;

    k_detect<<<1, 256>>>((const unsigned int*)ei, e);
    k_zero<<<(n + 255) / 256, 256>>>(n);
    k_deg<<<gridE, 256>>>(ei, e);
    k_scan1<<<nblk, SC>>>(n);
    k_scan2<<<1, MAXBLK>>>(nblk, n);
    k_scan3<<<nblk, SC>>>(n);
    k_fill<<<gridE, 256>>>(ei, e);
    k_pull1<<<gridP, 256>>>(x, n);
    k_mid<<<grid64, 256>>>(x, gcn_w1, gcn_b1, wl1, bl1, wr1, n);
    k_pull2<<<gridP, 256>>>(n);
    k_fin<<<grid64, 256>>>(gcn_w2, gcn_b2, wl2, bl2, wr2, lg, lb, sg, sb, pw, pb, out, n);
}